// round 1
// baseline (speedup 1.0000x reference)
#include <cuda_runtime.h>

#define DD   256
#define HID  1024
#define NL   4
#define NB   16
#define SEQ  4096
#define NC   10

__device__ __forceinline__ float gelu_tanh(float x) {
    const float k0 = 0.7978845608028654f;   // sqrt(2/pi)
    float x3 = x * x * x;
    return 0.5f * x * (1.0f + tanhf(k0 * (x + 0.044715f * x3)));
}

// Split matvec: out[j] = sum_d y[d] * W[d*DD + j], DD=256 reduction, 256 outputs.
// 256 threads = 64 output-quads (q) x 4 reduction slices (s).
__device__ __forceinline__ void matvec_256_256(
    const float* __restrict__ yin, const float* __restrict__ W,
    float* __restrict__ outv, float4* __restrict__ red, int t)
{
    int q = t & 63, s = t >> 6;
    const float4* W4 = (const float4*)W;   // [256 rows][64 float4]
    float4 acc = make_float4(0.f, 0.f, 0.f, 0.f);
    int d0 = s * 64;
#pragma unroll 8
    for (int d = 0; d < 64; ++d) {
        float yv = yin[d0 + d];
        float4 w = W4[(d0 + d) * 64 + q];
        acc.x += yv * w.x; acc.y += yv * w.y;
        acc.z += yv * w.z; acc.w += yv * w.w;
    }
    red[t] = acc;
    __syncthreads();
    if (s == 0) {
        float4 a = red[q], b = red[64 + q], c = red[128 + q], d = red[192 + q];
        outv[4 * q + 0] = a.x + b.x + c.x + d.x;
        outv[4 * q + 1] = a.y + b.y + c.y + d.y;
        outv[4 * q + 2] = a.z + b.z + c.z + d.z;
        outv[4 * q + 3] = a.w + b.w + c.w + d.w;
    }
    __syncthreads();
}

__global__ __launch_bounds__(256, 1) void performer_cls_kernel(
    const int*   __restrict__ x,
    const float* __restrict__ emb_tok,
    const float* __restrict__ emb_pos,
    const float* __restrict__ ln1_s, const float* __restrict__ ln1_b,
    const float* __restrict__ wv,    const float* __restrict__ wo,
    const float* __restrict__ bo,
    const float* __restrict__ ln2_s, const float* __restrict__ ln2_b,
    const float* __restrict__ w1,    const float* __restrict__ b1,
    const float* __restrict__ w2,    const float* __restrict__ b2,
    const float* __restrict__ w_cls, const float* __restrict__ b_cls,
    float* __restrict__ out)
{
    __shared__ float  sh_y[DD];
    __shared__ float  sh_v[DD];
    __shared__ float  sh_hid[HID];
    __shared__ float4 sh_red[256];
    __shared__ float  sh_warp[16];
    __shared__ float  sh_stat[2];

    const int b = blockIdx.x;
    const int t = threadIdx.x;
    const int lane = t & 31, wid = t >> 5;

    // h[b,0,:] = emb_tok[x[b,0]] + emb_pos[0]
    const int tok = x[b * SEQ];
    float h = emb_tok[tok * DD + t] + emb_pos[t];

    for (int l = 0; l < NL; ++l) {
        // ============ LN1 ============
        {
            float s1 = h, s2 = h * h;
#pragma unroll
            for (int o = 16; o; o >>= 1) {
                s1 += __shfl_xor_sync(0xffffffffu, s1, o);
                s2 += __shfl_xor_sync(0xffffffffu, s2, o);
            }
            if (lane == 0) { sh_warp[wid] = s1; sh_warp[8 + wid] = s2; }
            __syncthreads();
            if (t == 0) {
                float a = 0.f, c = 0.f;
#pragma unroll
                for (int i = 0; i < 8; ++i) { a += sh_warp[i]; c += sh_warp[8 + i]; }
                float mu = a * (1.0f / DD);
                float var = c * (1.0f / DD) - mu * mu;
                sh_stat[0] = mu;
                sh_stat[1] = rsqrtf(fmaxf(var, 0.f) + 1e-5f);
            }
            __syncthreads();
            sh_y[t] = (h - sh_stat[0]) * sh_stat[1] * ln1_s[l * DD + t] + ln1_b[l * DD + t];
            __syncthreads();
        }

        // ============ attention @ pos 0 == v[0]:  o = (y @ wv) @ wo + bo ============
        matvec_256_256(sh_y, wv + l * DD * DD, sh_v, sh_red, t);
        matvec_256_256(sh_v, wo + l * DD * DD, sh_y, sh_red, t);   // o lands in sh_y
        h += sh_y[t] + bo[l * DD + t];
        __syncthreads();

        // ============ LN2 ============
        {
            float s1 = h, s2 = h * h;
#pragma unroll
            for (int o = 16; o; o >>= 1) {
                s1 += __shfl_xor_sync(0xffffffffu, s1, o);
                s2 += __shfl_xor_sync(0xffffffffu, s2, o);
            }
            if (lane == 0) { sh_warp[wid] = s1; sh_warp[8 + wid] = s2; }
            __syncthreads();
            if (t == 0) {
                float a = 0.f, c = 0.f;
#pragma unroll
                for (int i = 0; i < 8; ++i) { a += sh_warp[i]; c += sh_warp[8 + i]; }
                float mu = a * (1.0f / DD);
                float var = c * (1.0f / DD) - mu * mu;
                sh_stat[0] = mu;
                sh_stat[1] = rsqrtf(fmaxf(var, 0.f) + 1e-5f);
            }
            __syncthreads();
            sh_y[t] = (h - sh_stat[0]) * sh_stat[1] * ln2_s[l * DD + t] + ln2_b[l * DD + t];
            __syncthreads();
        }

        // ============ MLP up: hid[4t..4t+3] = gelu(y2 @ w1 + b1) ============
        {
            const float4* W1_4 = (const float4*)(w1 + (size_t)l * DD * HID);  // [256 rows][256 float4]
            float4 acc = make_float4(0.f, 0.f, 0.f, 0.f);
#pragma unroll 8
            for (int d = 0; d < DD; ++d) {
                float yv = sh_y[d];
                float4 w = W1_4[d * 256 + t];
                acc.x += yv * w.x; acc.y += yv * w.y;
                acc.z += yv * w.z; acc.w += yv * w.w;
            }
            float4 bb = ((const float4*)(b1 + l * HID))[t];
            float4 g;
            g.x = gelu_tanh(acc.x + bb.x);
            g.y = gelu_tanh(acc.y + bb.y);
            g.z = gelu_tanh(acc.z + bb.z);
            g.w = gelu_tanh(acc.w + bb.w);
            ((float4*)sh_hid)[t] = g;
            __syncthreads();
        }

        // ============ MLP down: h += hid @ w2 + b2 ============
        {
            int q = t & 63, s = t >> 6;
            const float4* W2_4 = (const float4*)(w2 + (size_t)l * HID * DD);  // [1024 rows][64 float4]
            float4 acc = make_float4(0.f, 0.f, 0.f, 0.f);
            int d0 = s * 256;
#pragma unroll 8
            for (int d = 0; d < 256; ++d) {
                float hv = sh_hid[d0 + d];
                float4 w = W2_4[(d0 + d) * 64 + q];
                acc.x += hv * w.x; acc.y += hv * w.y;
                acc.z += hv * w.z; acc.w += hv * w.w;
            }
            sh_red[t] = acc;
            __syncthreads();
            if (s == 0) {
                float4 a = sh_red[q], bq = sh_red[64 + q], c = sh_red[128 + q], d = sh_red[192 + q];
                sh_v[4 * q + 0] = a.x + bq.x + c.x + d.x;
                sh_v[4 * q + 1] = a.y + bq.y + c.y + d.y;
                sh_v[4 * q + 2] = a.z + bq.z + c.z + d.z;
                sh_v[4 * q + 3] = a.w + bq.w + c.w + d.w;
            }
            __syncthreads();
            h += sh_v[t] + b2[l * DD + t];
            __syncthreads();
        }
    }

    // ============ classifier head: out[b, c] = h . w_cls[:, c] + b_cls[c] ============
    sh_y[t] = h;
    __syncthreads();
    if (t < NC) {
        float acc = b_cls[t];
#pragma unroll 8
        for (int d = 0; d < DD; ++d)
            acc += sh_y[d] * w_cls[d * NC + t];
        out[b * NC + t] = acc;
    }
}

extern "C" void kernel_launch(void* const* d_in, const int* in_sizes, int n_in,
                              void* d_out, int out_size)
{
    // metadata order (setup_inputs dict order):
    // 0:x 1:emb_tok 2:emb_pos 3:proj 4:ln1_s 5:ln1_b 6:wq 7:wk 8:wv 9:wo
    // 10:bo 11:ln2_s 12:ln2_b 13:w1 14:b1 15:w2 16:b2 17:w_cls 18:b_cls
    const int*   x       = (const int*)  d_in[0];
    const float* emb_tok = (const float*)d_in[1];
    const float* emb_pos = (const float*)d_in[2];
    const float* ln1_s   = (const float*)d_in[4];
    const float* ln1_b   = (const float*)d_in[5];
    const float* wv      = (const float*)d_in[8];
    const float* wo      = (const float*)d_in[9];
    const float* bo      = (const float*)d_in[10];
    const float* ln2_s   = (const float*)d_in[11];
    const float* ln2_b   = (const float*)d_in[12];
    const float* w1      = (const float*)d_in[13];
    const float* b1      = (const float*)d_in[14];
    const float* w2      = (const float*)d_in[15];
    const float* b2      = (const float*)d_in[16];
    const float* w_cls   = (const float*)d_in[17];
    const float* b_cls   = (const float*)d_in[18];
    float* out = (float*)d_out;

    performer_cls_kernel<<<NB, 256>>>(x, emb_tok, emb_pos, ln1_s, ln1_b,
                                      wv, wo, bo, ln2_s, ln2_b,
                                      w1, b1, w2, b2, w_cls, b_cls, out);
}

// round 2
// speedup vs baseline: 1.5787x; 1.5787x over previous
#include <cuda_runtime.h>

#define DD   256
#define HID  1024
#define NL   4
#define NB   16
#define SEQ  4096
#define NC   10

__device__ float g_h[NB * DD];
__device__ float g_v[NB * DD];
__device__ float g_hid[NB * HID];

__device__ __forceinline__ float gelu_tanh(float x) {
    const float k0 = 0.7978845608028654f;   // sqrt(2/pi)
    float x3 = x * x * x;
    return 0.5f * x * (1.0f + tanhf(k0 * (x + 0.044715f * x3)));
}

// Block-wide LayerNorm of a 256-vector (one value per thread) -> sh_y.
__device__ __forceinline__ void block_ln(
    float hval, const float* __restrict__ lns, const float* __restrict__ lnb,
    float* sh_y, float* sh_warp, float* sh_stat, int t)
{
    int lane = t & 31, wid = t >> 5;
    float s1 = hval, s2 = hval * hval;
#pragma unroll
    for (int o = 16; o; o >>= 1) {
        s1 += __shfl_xor_sync(0xffffffffu, s1, o);
        s2 += __shfl_xor_sync(0xffffffffu, s2, o);
    }
    if (lane == 0) { sh_warp[wid] = s1; sh_warp[8 + wid] = s2; }
    __syncthreads();
    if (t == 0) {
        float a = 0.f, c = 0.f;
#pragma unroll
        for (int i = 0; i < 8; ++i) { a += sh_warp[i]; c += sh_warp[8 + i]; }
        float mu = a * (1.0f / DD);
        float var = c * (1.0f / DD) - mu * mu;
        sh_stat[0] = mu;
        sh_stat[1] = rsqrtf(fmaxf(var, 0.f) + 1e-5f);
    }
    __syncthreads();
    sh_y[t] = (hval - sh_stat[0]) * sh_stat[1] * lns[t] + lnb[t];
    __syncthreads();
}

// ---------------- init: h[b] = emb_tok[x[b,0]] + emb_pos[0] ----------------
__global__ __launch_bounds__(256) void k_init(
    const int* __restrict__ x, const float* __restrict__ emb_tok,
    const float* __restrict__ emb_pos)
{
    int b = blockIdx.x, t = threadIdx.x;
    int tok = x[b * SEQ];
    g_h[b * DD + t] = emb_tok[tok * DD + t] + emb_pos[t];
}

// ---------------- K1: v = LN1(h) @ wv. grid 64 = 16 batches x 4 slices ----------------
__global__ __launch_bounds__(256) void k_attn_v(
    const float* __restrict__ W, const float* __restrict__ lns,
    const float* __restrict__ lnb)
{
    __shared__ float  sh_y[DD];
    __shared__ float4 sh_red[16][16];   // [slice][quad]
    __shared__ float  sh_warp[16], sh_stat[2];
    int b = blockIdx.x >> 2, s4 = blockIdx.x & 3, t = threadIdx.x;

    block_ln(g_h[b * DD + t], lns, lnb, sh_y, sh_warp, sh_stat, t);

    int q = t & 15, sl = t >> 4;
    const float4* W4 = (const float4*)W;   // [256 rows][64 quads]
    float4 acc = make_float4(0.f, 0.f, 0.f, 0.f);
    int d0 = sl * 16, jq = s4 * 16 + q;
#pragma unroll
    for (int d = 0; d < 16; ++d) {
        float yv = sh_y[d0 + d];
        float4 w = W4[(d0 + d) * 64 + jq];
        acc.x += yv * w.x; acc.y += yv * w.y;
        acc.z += yv * w.z; acc.w += yv * w.w;
    }
    sh_red[sl][q] = acc;
    __syncthreads();
    if (t < 16) {
        float4 a = sh_red[0][t];
#pragma unroll
        for (int s = 1; s < 16; ++s) {
            float4 r = sh_red[s][t];
            a.x += r.x; a.y += r.y; a.z += r.z; a.w += r.w;
        }
        ((float4*)(g_v + b * DD + s4 * 64))[t] = a;
    }
}

// ---------------- K2: h += v @ wo + bo. grid 64 ----------------
__global__ __launch_bounds__(256) void k_attn_o(
    const float* __restrict__ W, const float* __restrict__ bo)
{
    __shared__ float  sh_y[DD];
    __shared__ float4 sh_red[16][16];
    int b = blockIdx.x >> 2, s4 = blockIdx.x & 3, t = threadIdx.x;

    sh_y[t] = g_v[b * DD + t];
    __syncthreads();

    int q = t & 15, sl = t >> 4;
    const float4* W4 = (const float4*)W;
    float4 acc = make_float4(0.f, 0.f, 0.f, 0.f);
    int d0 = sl * 16, jq = s4 * 16 + q;
#pragma unroll
    for (int d = 0; d < 16; ++d) {
        float yv = sh_y[d0 + d];
        float4 w = W4[(d0 + d) * 64 + jq];
        acc.x += yv * w.x; acc.y += yv * w.y;
        acc.z += yv * w.z; acc.w += yv * w.w;
    }
    sh_red[sl][q] = acc;
    __syncthreads();
    if (t < 16) {
        float4 a = sh_red[0][t];
#pragma unroll
        for (int s = 1; s < 16; ++s) {
            float4 r = sh_red[s][t];
            a.x += r.x; a.y += r.y; a.z += r.z; a.w += r.w;
        }
        float4 ho = ((const float4*)(g_h + b * DD + s4 * 64))[t];
        float4 bb = ((const float4*)(bo + s4 * 64))[t];
        a.x += ho.x + bb.x; a.y += ho.y + bb.y;
        a.z += ho.z + bb.z; a.w += ho.w + bb.w;
        ((float4*)(g_h + b * DD + s4 * 64))[t] = a;
    }
}

// ---------------- K3: hid = gelu(LN2(h) @ w1 + b1). grid 128 = 16 x 8 slices ----------------
__global__ __launch_bounds__(256) void k_mlp_up(
    const float* __restrict__ W, const float* __restrict__ bias,
    const float* __restrict__ lns, const float* __restrict__ lnb)
{
    __shared__ float  sh_y[DD];
    __shared__ float4 sh_red[8][32];    // [slice][quad]
    __shared__ float  sh_warp[16], sh_stat[2];
    int b = blockIdx.x >> 3, s8 = blockIdx.x & 7, t = threadIdx.x;

    block_ln(g_h[b * DD + t], lns, lnb, sh_y, sh_warp, sh_stat, t);

    int q = t & 31, sl = t >> 5;
    const float4* W4 = (const float4*)W;   // [256 rows][256 quads]
    float4 acc = make_float4(0.f, 0.f, 0.f, 0.f);
    int d0 = sl * 32, jq = s8 * 32 + q;
#pragma unroll
    for (int d = 0; d < 32; ++d) {
        float yv = sh_y[d0 + d];
        float4 w = W4[(d0 + d) * 256 + jq];
        acc.x += yv * w.x; acc.y += yv * w.y;
        acc.z += yv * w.z; acc.w += yv * w.w;
    }
    sh_red[sl][q] = acc;
    __syncthreads();
    if (t < 32) {
        float4 a = sh_red[0][t];
#pragma unroll
        for (int s = 1; s < 8; ++s) {
            float4 r = sh_red[s][t];
            a.x += r.x; a.y += r.y; a.z += r.z; a.w += r.w;
        }
        float4 bb = ((const float4*)bias)[s8 * 32 + t];
        float4 g;
        g.x = gelu_tanh(a.x + bb.x);
        g.y = gelu_tanh(a.y + bb.y);
        g.z = gelu_tanh(a.z + bb.z);
        g.w = gelu_tanh(a.w + bb.w);
        ((float4*)(g_hid + b * HID + s8 * 128))[t] = g;
    }
}

// ---------------- K4: h += hid @ w2 + b2. grid 128 = 16 x 8 slices ----------------
__global__ __launch_bounds__(256) void k_mlp_down(
    const float* __restrict__ W, const float* __restrict__ bias)
{
    __shared__ float4 sh_hid4[HID / 4];
    __shared__ float4 sh_red[32][8];    // [slice][quad]
    __shared__ float4 sh_red2[8][8];    // [group][quad]
    int b = blockIdx.x >> 3, s8 = blockIdx.x & 7, t = threadIdx.x;

    sh_hid4[t] = ((const float4*)(g_hid + b * HID))[t];
    __syncthreads();
    const float* sh_hid = (const float*)sh_hid4;

    int q = t & 7, sl = t >> 3;
    const float4* W4 = (const float4*)W;   // [1024 rows][64 quads]
    float4 acc = make_float4(0.f, 0.f, 0.f, 0.f);
    int d0 = sl * 32, jq = s8 * 8 + q;
#pragma unroll
    for (int d = 0; d < 32; ++d) {
        float hv = sh_hid[d0 + d];
        float4 w = W4[(d0 + d) * 64 + jq];
        acc.x += hv * w.x; acc.y += hv * w.y;
        acc.z += hv * w.z; acc.w += hv * w.w;
    }
    sh_red[sl][q] = acc;
    __syncthreads();
    if (t < 64) {                       // stage 1: 32 -> 8 partials per quad
        int qq = t & 7, g = t >> 3;
        float4 a = sh_red[g * 4][qq];
#pragma unroll
        for (int k = 1; k < 4; ++k) {
            float4 r = sh_red[g * 4 + k][qq];
            a.x += r.x; a.y += r.y; a.z += r.z; a.w += r.w;
        }
        sh_red2[g][qq] = a;
    }
    __syncthreads();
    if (t < 8) {                        // stage 2: final 8 -> 1
        float4 a = sh_red2[0][t];
#pragma unroll
        for (int g = 1; g < 8; ++g) {
            float4 r = sh_red2[g][t];
            a.x += r.x; a.y += r.y; a.z += r.z; a.w += r.w;
        }
        float4 bb = ((const float4*)bias)[s8 * 8 + t];
        float4 ho = ((const float4*)(g_h + b * DD + s8 * 32))[t];
        a.x += bb.x + ho.x; a.y += bb.y + ho.y;
        a.z += bb.z + ho.z; a.w += bb.w + ho.w;
        ((float4*)(g_h + b * DD + s8 * 32))[t] = a;
    }
}

// ---------------- head: out[b,c] = h[b] . w_cls[:,c] + b_cls[c] ----------------
__global__ __launch_bounds__(256) void k_head(
    const float* __restrict__ w_cls, const float* __restrict__ b_cls,
    float* __restrict__ out)
{
    __shared__ float sh_h[DD];
    int b = blockIdx.x, t = threadIdx.x;
    sh_h[t] = g_h[b * DD + t];
    __syncthreads();
    if (t < NC) {
        float acc = b_cls[t];
#pragma unroll 8
        for (int d = 0; d < DD; ++d)
            acc += sh_h[d] * w_cls[d * NC + t];
        out[b * NC + t] = acc;
    }
}

extern "C" void kernel_launch(void* const* d_in, const int* in_sizes, int n_in,
                              void* d_out, int out_size)
{
    // 0:x 1:emb_tok 2:emb_pos 3:proj 4:ln1_s 5:ln1_b 6:wq 7:wk 8:wv 9:wo
    // 10:bo 11:ln2_s 12:ln2_b 13:w1 14:b1 15:w2 16:b2 17:w_cls 18:b_cls
    const int*   x       = (const int*)  d_in[0];
    const float* emb_tok = (const float*)d_in[1];
    const float* emb_pos = (const float*)d_in[2];
    const float* ln1_s   = (const float*)d_in[4];
    const float* ln1_b   = (const float*)d_in[5];
    const float* wv      = (const float*)d_in[8];
    const float* wo      = (const float*)d_in[9];
    const float* bo      = (const float*)d_in[10];
    const float* ln2_s   = (const float*)d_in[11];
    const float* ln2_b   = (const float*)d_in[12];
    const float* w1      = (const float*)d_in[13];
    const float* b1      = (const float*)d_in[14];
    const float* w2      = (const float*)d_in[15];
    const float* b2      = (const float*)d_in[16];
    const float* w_cls   = (const float*)d_in[17];
    const float* b_cls   = (const float*)d_in[18];
    float* out = (float*)d_out;

    k_init<<<NB, 256>>>(x, emb_tok, emb_pos);
    for (int l = 0; l < NL; ++l) {
        size_t oDD = (size_t)l * DD * DD;
        k_attn_v<<<64, 256>>>(wv + oDD, ln1_s + l * DD, ln1_b + l * DD);
        k_attn_o<<<64, 256>>>(wo + oDD, bo + l * DD);
        k_mlp_up<<<128, 256>>>(w1 + (size_t)l * DD * HID, b1 + l * HID,
                               ln2_s + l * DD, ln2_b + l * DD);
        k_mlp_down<<<128, 256>>>(w2 + (size_t)l * HID * DD, b2 + l * DD);
    }
    k_head<<<NB, 256>>>(w_cls, b_cls, out);
}